// round 16
// baseline (speedup 1.0000x reference)
#include <cuda_runtime.h>
#include <math.h>
#include <stdint.h>

#define L   401
#define B   256
#define LL  (L * L)
#define NCHUNK 4                 // batch chunks in main grid
#define BCHUNK (B / NCHUNK)      // 64 batches per main block (2 bit-plane words)
#define PW  (3 * L)              // words per batch-word slab: [plane][j]
#define NBLK (NCHUNK * L)        // 1604 main blocks
#define NT  512

// ---------------- device globals ----------------
__device__ float    g_bins[L * 32];        // one bin per 128B line: bin d at [d*32]
__device__ float    g_scf[2 * 32];         // [0]=ctcf_num, [32]=within_num
__device__ int      g_sci[2 * 32];         // [0]=nc_sum,   [32]=cnt_within (exact ints)
__device__ uint32_t g_planes[8 * PW];      // [batch_word][plane f/r/c][j], bit = b%32
__device__ unsigned int g_done;

// ---------------- kernel 1: merged prep (planes + analytic counts) ----------------
__global__ __launch_bounds__(512) void prep_kernel(const int* __restrict__ ctcf,
                                                   const float* __restrict__ logits) {
    const int blk = blockIdx.x;
    const int t   = threadIdx.x;

    if (blk < L) {
        if (t < B) {
            const int p = blk, b = t;
            int o = ctcf[b * L + p];
            float l0 = logits[(b * L + p) * 2 + 0];
            float l1 = logits[(b * L + p) * 2 + 1];
            uint32_t bf = __ballot_sync(0xffffffffu, o == 1);
            uint32_t br = __ballot_sync(0xffffffffu, o == -1);
            uint32_t bc = __ballot_sync(0xffffffffu, l1 > l0);
            if ((b & 31) == 0) {
                int w = b >> 5;
                g_planes[w * PW + 0 * L + p] = bf;
                g_planes[w * PW + 1 * L + p] = br;
                g_planes[w * PW + 2 * L + p] = bc;
            }
        }
    } else {
        const int b = blk - L;
        const int p = t;
        __shared__ int cnt[5];                 // A, F, R, n1, adjEq
        __shared__ unsigned char compsh[L];
        if (p < 5) cnt[p] = 0;
        __syncthreads();

        int a = 0, f = 0, r = 0, c = 0;
        if (p < L) {
            int o = ctcf[b * L + p];
            a = (o != 0);
            f = (o == 1);
            r = (o == -1);
            float l0 = logits[(b * L + p) * 2 + 0];
            float l1 = logits[(b * L + p) * 2 + 1];
            c = (l1 > l0);                     // argmax, ties -> 0
            compsh[p] = (unsigned char)c;
        }
        __syncthreads();

        int adj = 0;
        if (p < L - 1) adj = (compsh[p] == compsh[p + 1]);

        atomicAdd(&cnt[0], a);
        atomicAdd(&cnt[1], f);
        atomicAdd(&cnt[2], r);
        atomicAdd(&cnt[3], c);
        atomicAdd(&cnt[4], adj);
        __syncthreads();

        if (p == 0) {
            int A = cnt[0], F = cnt[1], R = cnt[2], n1 = cnt[3];
            int n0 = L - n1;
            int nc = A * A - F * R;                            // non_conv count (exact)
            int cw = n0 * n0 + n1 * n1 - L - 2 * cnt[4];       // same & d>=2 (exact)
            atomicAdd(&g_sci[0],  nc);
            atomicAdd(&g_sci[32], cw);
        }
    }
}

// ---------------- kernel 2: aligned-float4 streaming + last-block finalize ----------
// block = (batch chunk, row i), 512 threads. Batch-residue class c = b%4 has a
// CONSTANT row misalignment, so its float4 groups are 16B-aligned. Threads 0..397
// own one (class, float4-group); threads 398..409 cover the 12 leftover scalar
// columns. Every (b, j) element is covered exactly once. MLP=4 via staged loads.
__global__ __launch_bounds__(NT, 2) void main_kernel(const float* __restrict__ cm,
                                                     float* __restrict__ out) {
    const int i   = blockIdx.y;
    const int tid = threadIdx.x;
    const int w0  = blockIdx.x * 2;        // first batch-word of this chunk
    const int b0  = blockIdx.x * BCHUNK;

    __shared__ uint32_t shp[2 * PW];       // 9.6 KB: the 2 batch-words this block needs

    // ---- bulk L2 prefetch of this block's 64 row-slices (TMA engine) ----
    if (tid < BCHUNK) {
        const char* cmb = (const char*)cm;
        const size_t total = (size_t)B * LL * 4u;
        const size_t e = ((size_t)(b0 + tid) * LL + (size_t)i * L) * 4u;
        const char* src = cmb + e;
        const uint32_t fr = (uint32_t)((uintptr_t)src & 15u);
        const char* wnd = src - fr;
        uint32_t sz = 1616u;
        if (e - fr + 1616u > total) sz = 1600u;
        asm volatile("cp.async.bulk.prefetch.L2.global [%0], %1;"
                     :: "l"(wnd), "r"(sz) : "memory");
    }

    for (int idx = tid; idx < 2 * PW; idx += NT)
        shp[idx] = g_planes[w0 * PW + idx];
    __syncthreads();

    // per-class alignment geometry (base_off: element alignment of cm, usually 0)
    const uint32_t base_off = (uint32_t)(((uintptr_t)cm >> 2) & 3u);
    const int pad0 = (int)((4u - ((base_off + 0 + i) & 3u)) & 3u), G0 = (401 - pad0) >> 2;
    const int pad1 = (int)((4u - ((base_off + 1 + i) & 3u)) & 3u), G1 = (401 - pad1) >> 2;
    const int pad2 = (int)((4u - ((base_off + 2 + i) & 3u)) & 3u), G2 = (401 - pad2) >> 2;
    const int pad3 = (int)((4u - ((base_off + 3 + i) & 3u)) & 3u), G3 = (401 - pad3) >> 2;
    const int p1 = G0, p2 = G0 + G1, p3 = G0 + G1 + G2, p4t = p3 + G3;   // p4t == 398

    float ct = 0.f, wn = 0.f;

    if (tid < p4t) {
        int c, g, padc;
        if      (tid < p1) { c = 0; g = tid;      padc = pad0; }
        else if (tid < p2) { c = 1; g = tid - p1; padc = pad1; }
        else if (tid < p3) { c = 2; g = tid - p2; padc = pad2; }
        else               { c = 3; g = tid - p3; padc = pad3; }
        const int jb = padc + 4 * g;

        // per-column masks, both 32-batch words (static indexing after unroll)
        uint32_t M10[2][4], M20[2][4];
#pragma unroll
        for (int h = 0; h < 2; ++h) {
            const uint32_t* s = shp + h * PW;
            const uint32_t fi = s[i], ri = s[L + i], ci = s[2 * L + i];
            const uint32_t ai = fi | ri;
#pragma unroll
            for (int k = 0; k < 4; ++k) {
                const int j = jb + k;
                const uint32_t fj = s[j], rj = s[L + j], cj = s[2 * L + j];
                M10[h][k] = ai & (fj | rj) & ~(fi & rj);
                M20[h][k] = (abs(i - j) >= 2) ? ~(ci ^ cj) : 0u;
            }
        }

        float acc0 = 0.f, acc1 = 0.f, acc2 = 0.f, acc3 = 0.f;
        const float4* pf = reinterpret_cast<const float4*>(
            cm + (size_t)(b0 + c) * LL + (size_t)i * L + jb);

#pragma unroll
        for (int so = 0; so < 4; ++so) {
            // stage 4 independent float4 loads (batch stride 4*LL floats = LL float4)
            float4 v[4];
#pragma unroll
            for (int k = 0; k < 4; ++k)
                v[k] = __ldcs(pf + (size_t)(so * 4 + k) * LL);

#pragma unroll
            for (int k = 0; k < 4; ++k) {
                const int sp = so * 4 + k;     // batch step 0..15 (compile-time)
                const int h  = sp >> 3;
                const int sh = c + 4 * (sp & 7);
                acc0 += v[k].x; acc1 += v[k].y; acc2 += v[k].z; acc3 += v[k].w;
                if ((M10[h][0] >> sh) & 1u) ct += fmaxf(v[k].x, 0.f);
                if ((M10[h][1] >> sh) & 1u) ct += fmaxf(v[k].y, 0.f);
                if ((M10[h][2] >> sh) & 1u) ct += fmaxf(v[k].z, 0.f);
                if ((M10[h][3] >> sh) & 1u) ct += fmaxf(v[k].w, 0.f);
                if ((M20[h][0] >> sh) & 1u) wn += v[k].x;
                if ((M20[h][1] >> sh) & 1u) wn += v[k].y;
                if ((M20[h][2] >> sh) & 1u) wn += v[k].z;
                if ((M20[h][3] >> sh) & 1u) wn += v[k].w;
            }
        }
        atomicAdd(&g_bins[abs(i - (jb + 0)) * 32], acc0);
        atomicAdd(&g_bins[abs(i - (jb + 1)) * 32], acc1);
        atomicAdd(&g_bins[abs(i - (jb + 2)) * 32], acc2);
        atomicAdd(&g_bins[abs(i - (jb + 3)) * 32], acc3);
    } else if (tid < p4t + 12) {
        // 12 leftover scalar columns (class heads/tails not covered by float4s)
        int l = tid - p4t;
        const int n0 = pad0 + ((401 - pad0) & 3);
        const int n1 = pad1 + ((401 - pad1) & 3);
        const int n2 = pad2 + ((401 - pad2) & 3);
        int c, j;
        if (l < n0) { c = 0; j = (l < pad0) ? l : pad0 + 4 * G0 + (l - pad0); }
        else {
            l -= n0;
            if (l < n1) { c = 1; j = (l < pad1) ? l : pad1 + 4 * G1 + (l - pad1); }
            else {
                l -= n1;
                if (l < n2) { c = 2; j = (l < pad2) ? l : pad2 + 4 * G2 + (l - pad2); }
                else { l -= n2; c = 3; j = (l < pad3) ? l : pad3 + 4 * G3 + (l - pad3); }
            }
        }
        const int d = abs(i - j);
        uint32_t M10[2], M20[2];
#pragma unroll
        for (int h = 0; h < 2; ++h) {
            const uint32_t* s = shp + h * PW;
            const uint32_t fi = s[i], ri = s[L + i], ci = s[2 * L + i];
            const uint32_t ai = fi | ri;
            const uint32_t fj = s[j], rj = s[L + j], cj = s[2 * L + j];
            M10[h] = ai & (fj | rj) & ~(fi & rj);
            M20[h] = (d >= 2) ? ~(ci ^ cj) : 0u;
        }
        float acc = 0.f;
        const float* p = cm + (size_t)(b0 + c) * LL + (size_t)i * L + j;
#pragma unroll
        for (int so = 0; so < 4; ++so) {
            float v[4];
#pragma unroll
            for (int k = 0; k < 4; ++k)
                v[k] = __ldcs(p + (size_t)(so * 4 + k) * 4 * LL);
#pragma unroll
            for (int k = 0; k < 4; ++k) {
                const int sp = so * 4 + k;
                const int h  = sp >> 3;
                const int sh = c + 4 * (sp & 7);
                acc += v[k];
                if ((M10[h] >> sh) & 1u) ct += fmaxf(v[k], 0.f);
                if ((M20[h] >> sh) & 1u) wn += v[k];
            }
        }
        atomicAdd(&g_bins[d * 32], acc);
    }

    // block-reduce scalars -> one float atomic each
    for (int o = 16; o; o >>= 1) {
        ct += __shfl_down_sync(0xffffffffu, ct, o);
        wn += __shfl_down_sync(0xffffffffu, wn, o);
    }
    __shared__ float red[2][16];
    const int wid = tid >> 5, lane = tid & 31;
    if (lane == 0) { red[0][wid] = ct; red[1][wid] = wn; }
    __syncthreads();
    if (tid == 0) {
        float cs = 0.f, ws = 0.f;
#pragma unroll
        for (int k = 0; k < 16; ++k) { cs += red[0][k]; ws += red[1][k]; }
        atomicAdd(&g_scf[0],  cs);
        atomicAdd(&g_scf[32], ws);
    }

    // ---------- last-block finalize ----------
    __threadfence();
    __shared__ unsigned int rank_sh;
    if (tid == 0) rank_sh = atomicAdd(&g_done, 1u);
    __syncthreads();
    if (rank_sh != NBLK - 1) return;
    __threadfence();

    float w0_ = 0.f, ld0 = 0.f, lp0 = 0.f;
    float v4a[4] = {0.f, 0.f, 0.f, 0.f};    // n, sum(w*ld), sum(w*lp), masked-sum
    if (tid < L) {
        float binv = g_bins[tid * 32];
        float cntp = (tid == 0) ? (float)L : 2.0f * (float)(L - tid);
        float mc = binv / (cntp * (float)B);
        bool valid = (tid >= 2) && isfinite(mc) && (mc > 0.0f);
        w0_ = valid ? 1.f : 0.f;
        ld0 = logf(fmaxf((float)tid, 1.0f));
        lp0 = logf((valid ? mc : 1.0f) + 1e-6f);
        v4a[0] = w0_; v4a[1] = w0_ * ld0; v4a[2] = w0_ * lp0;
        if (tid >= 2) v4a[3] = binv;
    }

    __shared__ float sc4[4][16];
    __shared__ float tot[4];
#pragma unroll
    for (int o = 16; o; o >>= 1)
#pragma unroll
        for (int q = 0; q < 4; ++q) v4a[q] += __shfl_down_sync(0xffffffffu, v4a[q], o);
    if (lane == 0) { sc4[0][wid] = v4a[0]; sc4[1][wid] = v4a[1]; sc4[2][wid] = v4a[2]; sc4[3][wid] = v4a[3]; }
    __syncthreads();
    if (tid < 4) {
        float sAcc = 0.f;
#pragma unroll
        for (int k = 0; k < 16; ++k) sAcc += sc4[tid][k];
        tot[tid] = sAcc;
    }
    __syncthreads();

    const float n  = tot[0];
    const float ns = fmaxf(n, 1.0f);
    const float xm = tot[1] / ns, ym = tot[2] / ns;
    const float msk = tot[3];

    float v2[2];
    v2[0] = w0_ * (ld0 - xm) * (lp0 - ym);
    v2[1] = w0_ * (ld0 - xm) * (ld0 - xm);
#pragma unroll
    for (int o = 16; o; o >>= 1)
#pragma unroll
        for (int q = 0; q < 2; ++q) v2[q] += __shfl_down_sync(0xffffffffu, v2[q], o);
    if (lane == 0) { sc4[0][wid] = v2[0]; sc4[1][wid] = v2[1]; }
    __syncthreads();
    if (tid == 0) {
        float num = 0.f, den = 0.f;
#pragma unroll
        for (int k = 0; k < 16; ++k) { num += sc4[0][k]; den += sc4[1][k]; }

        // distance decay
        double slope = (double)num / ((double)den + 1e-8);
        double dist  = (n >= 5.0f) ? (slope + 0.85) * (slope + 0.85) : 0.0;
        // ctcf
        double ncs   = (double)g_sci[0];
        double hinge = (double)g_scf[0] / (ncs + 1e-6);
        double ctcfl = (ncs < 1.0) ? 0.0 : hinge;
        // compartment
        double cw      = (double)g_sci[32];
        double cb      = 159600.0 * (double)B - cw;   // (L-1)(L-2) masked pairs per batch
        double within  = (double)g_scf[32] / fmax(cw, 1.0);
        double between = ((double)msk - (double)g_scf[32]) / fmax(cb, 1.0);
        double ratio   = within / (fabs(between) + 1e-6);
        double compl_  = fmax(1.5 - ratio, 0.0);

        out[0] = (float)dist;
        out[1] = (float)ctcfl;
        out[2] = (float)compl_;
        out[3] = (float)(dist + 0.5 * ctcfl + 0.5 * compl_);
    }

    // ---------- reset state for next replay ----------
    __syncthreads();
    if (tid < L) g_bins[tid * 32] = 0.f;
    if (tid < 2) { g_scf[tid * 32] = 0.f; g_sci[tid * 32] = 0; }
    if (tid == 0) g_done = 0u;
}

// ---------------- launch ----------------
extern "C" void kernel_launch(void* const* d_in, const int* in_sizes, int n_in,
                              void* d_out, int out_size) {
    const float* cm     = (const float*)d_in[0];   // (B, L, L) f32
    const float* logits = (const float*)d_in[1];   // (B, L, 2) f32
    const int*   ctcf   = (const int*)d_in[2];     // (B, L)    i32
    float*       out    = (float*)d_out;           // 4 f32

    prep_kernel<<<L + B, 512>>>(ctcf, logits);
    dim3 grid(NCHUNK, L);
    main_kernel<<<grid, NT>>>(cm, out);
}

// round 17
// speedup vs baseline: 1.3010x; 1.3010x over previous
#include <cuda_runtime.h>
#include <math.h>
#include <stdint.h>

#define L   401
#define B   256
#define LL  (L * L)
#define NCHUNK 4                 // batch chunks in main grid
#define BCHUNK (B / NCHUNK)      // 64 batches per main block (2 bit-plane words)
#define PW  (3 * L)              // words per batch-word slab: [plane][j]
#define NBLK (NCHUNK * L)        // 1604 main blocks

// ---------------- device globals ----------------
__device__ float    g_bins[L * 32];        // one bin per 128B line: bin d at [d*32]
__device__ float    g_scf[2 * 32];         // [0]=ctcf_num, [32]=within_num
__device__ int      g_sci[2 * 32];         // [0]=nc_sum,   [32]=cnt_within (exact ints)
__device__ uint32_t g_planes[8 * PW];      // [batch_word][plane f/r/c][j], bit = b%32
__device__ unsigned int g_done;

static __device__ __forceinline__ uint32_t s2u(const void* p) {
    return (uint32_t)__cvta_generic_to_shared(p);
}
static __device__ __forceinline__ void cp4(uint32_t d, const float* g) {
    asm volatile("cp.async.ca.shared.global [%0], [%1], 4;" :: "r"(d), "l"(g) : "memory");
}

// ---------------- kernel 1: merged prep (planes + analytic counts) ----------------
__global__ __launch_bounds__(512) void prep_kernel(const int* __restrict__ ctcf,
                                                   const float* __restrict__ logits) {
    const int blk = blockIdx.x;
    const int t   = threadIdx.x;

    if (blk < L) {
        if (t < B) {
            const int p = blk, b = t;
            int o = ctcf[b * L + p];
            float l0 = logits[(b * L + p) * 2 + 0];
            float l1 = logits[(b * L + p) * 2 + 1];
            uint32_t bf = __ballot_sync(0xffffffffu, o == 1);
            uint32_t br = __ballot_sync(0xffffffffu, o == -1);
            uint32_t bc = __ballot_sync(0xffffffffu, l1 > l0);
            if ((b & 31) == 0) {
                int w = b >> 5;
                g_planes[w * PW + 0 * L + p] = bf;
                g_planes[w * PW + 1 * L + p] = br;
                g_planes[w * PW + 2 * L + p] = bc;
            }
        }
    } else {
        const int b = blk - L;
        const int p = t;
        __shared__ int cnt[5];                 // A, F, R, n1, adjEq
        __shared__ unsigned char compsh[L];
        if (p < 5) cnt[p] = 0;
        __syncthreads();

        int a = 0, f = 0, r = 0, c = 0;
        if (p < L) {
            int o = ctcf[b * L + p];
            a = (o != 0);
            f = (o == 1);
            r = (o == -1);
            float l0 = logits[(b * L + p) * 2 + 0];
            float l1 = logits[(b * L + p) * 2 + 1];
            c = (l1 > l0);                     // argmax, ties -> 0
            compsh[p] = (unsigned char)c;
        }
        __syncthreads();

        int adj = 0;
        if (p < L - 1) adj = (compsh[p] == compsh[p + 1]);

        atomicAdd(&cnt[0], a);
        atomicAdd(&cnt[1], f);
        atomicAdd(&cnt[2], r);
        atomicAdd(&cnt[3], c);
        atomicAdd(&cnt[4], adj);
        __syncthreads();

        if (p == 0) {
            int A = cnt[0], F = cnt[1], R = cnt[2], n1 = cnt[3];
            int n0 = L - n1;
            int nc = A * A - F * R;                            // non_conv count (exact)
            int cw = n0 * n0 + n1 * n1 - L - 2 * cnt[4];       // same & d>=2 (exact)
            atomicAdd(&g_sci[0],  nc);
            atomicAdd(&g_sci[32], cw);
        }
    }
}

// ---------------- kernel 2: dual-path streaming + last-block finalize ----------
// block = (batch chunk, row i); thread tid owns j0 = tid and (tid<145) j1 = tid+256.
// Word 0 (32 batches): demand-LDG loop (MSHR pool). Word 1 (32 batches): cp.async
// 4B element copies into smem (separate async pool), issued fire-and-forget before
// each LDG phase and consumed after cp.async.wait_all. Each thread copies/reads
// ONLY its own columns -> per-thread wait suffices, no cross-thread sync.
__global__ __launch_bounds__(256) void main_kernel(const float* __restrict__ cm,
                                                   float* __restrict__ out) {
    const int i   = blockIdx.y;
    const int tid = threadIdx.x;
    const int w0  = blockIdx.x * 2;        // first batch-word of this chunk
    const int b0  = blockIdx.x * BCHUNK;

    __shared__ float buf[16][404];         // 25.9 KB: 16 cp rows, per-thread columns
    __shared__ uint32_t shp[2 * PW];       // 9.6 KB plane slab

    // ---- TMA L2 prefetch of the LDG half's 32 row-slices ----
    if (tid < 32) {
        const char* cmb = (const char*)cm;
        const size_t total = (size_t)B * LL * 4u;
        const size_t e = ((size_t)(b0 + tid) * LL + (size_t)i * L) * 4u;
        const char* src = cmb + e;
        const uint32_t fr = (uint32_t)((uintptr_t)src & 15u);
        const char* wnd = src - fr;
        uint32_t sz = 1616u;
        if (e - fr + 1616u > total) sz = 1600u;
        asm volatile("cp.async.bulk.prefetch.L2.global [%0], %1;"
                     :: "l"(wnd), "r"(sz) : "memory");
    }

    for (int idx = tid; idx < 2 * PW; idx += 256)
        shp[idx] = g_planes[w0 * PW + idx];
    __syncthreads();

    const int  j0   = tid;
    const int  j1   = tid + 256;
    const bool has1 = (j1 < L);
    const int  d0   = abs(i - j0);
    const int  d1   = has1 ? abs(i - j1) : 0;

    // masks for both 32-batch words
    uint32_t T10[2], T20[2], T11[2], T21[2];
#pragma unroll
    for (int h = 0; h < 2; ++h) {
        const uint32_t* s = shp + h * PW;
        const uint32_t fi = s[i], ri = s[L + i], ci = s[2 * L + i];
        const uint32_t ai = fi | ri;
        const uint32_t fj = s[j0], rj = s[L + j0], cj = s[2 * L + j0];
        T10[h] = ai & (fj | rj) & ~(fi & rj);    // ctcf pair & not convergent
        T20[h] = (d0 >= 2) ? ~(ci ^ cj) : 0u;    // same compartment & d>=2
        T11[h] = 0u; T21[h] = 0u;
        if (has1) {
            uint32_t fk = s[j1], rk = s[L + j1], ck = s[2 * L + j1];
            T11[h] = ai & (fk | rk) & ~(fi & rk);
            T21[h] = (d1 >= 2) ? ~(ci ^ ck) : 0u;
        }
    }

    float s0 = 0.f, s1 = 0.f, ct = 0.f, wn = 0.f;
    const float* base = cm + (size_t)b0 * LL + (size_t)i * L + j0;          // LDG word 0
    const float* srcB = cm + (size_t)(b0 + 32) * LL + (size_t)i * L;        // cp word 1

#pragma unroll
    for (int ph = 0; ph < 2; ++ph) {       // two 16-batch phases
        const int rb = ph * 16;            // row/batch offset within each word

        // ---- issue cp.async for word1 rows rb..rb+15 (own columns only) ----
#pragma unroll
        for (int bb = 0; bb < 16; ++bb) {
            const float* g = srcB + (size_t)(rb + bb) * LL;
            cp4(s2u(&buf[bb][0]) + (uint32_t)(j0 * 4), g + j0);
            if (has1) cp4(s2u(&buf[bb][0]) + (uint32_t)(j1 * 4), g + j1);
        }

        // ---- LDG loop: word0 batches rb..rb+15, batched 8 ----
#pragma unroll
        for (int c4 = 0; c4 < 2; ++c4) {
            float v0[8], v1[8];
#pragma unroll
            for (int k = 0; k < 8; ++k)
                v0[k] = __ldcs(base + (rb + c4 * 8 + k) * LL);
            if (has1) {
#pragma unroll
                for (int k = 0; k < 8; ++k)
                    v1[k] = __ldcs(base + (rb + c4 * 8 + k) * LL + 256);
            }
#pragma unroll
            for (int k = 0; k < 8; ++k) {
                const int kk = rb + c4 * 8 + k;
                float v = v0[k];
                s0 += v;
                if ((T10[0] >> kk) & 1u) ct += fmaxf(v, 0.f);
                if ((T20[0] >> kk) & 1u) wn += v;
            }
            if (has1) {
#pragma unroll
                for (int k = 0; k < 8; ++k) {
                    const int kk = rb + c4 * 8 + k;
                    float u = v1[k];
                    s1 += u;
                    if ((T11[0] >> kk) & 1u) ct += fmaxf(u, 0.f);
                    if ((T21[0] >> kk) & 1u) wn += u;
                }
            }
        }

        // ---- consume cp half (own columns; own cps complete after wait_all) ----
        asm volatile("cp.async.wait_all;" ::: "memory");
#pragma unroll
        for (int bb = 0; bb < 16; ++bb) {
            const int kk = rb + bb;        // bit in word-1 masks
            float v = buf[bb][j0];
            s0 += v;
            if ((T10[1] >> kk) & 1u) ct += fmaxf(v, 0.f);
            if ((T20[1] >> kk) & 1u) wn += v;
            if (has1) {
                float u = buf[bb][j1];
                s1 += u;
                if ((T11[1] >> kk) & 1u) ct += fmaxf(u, 0.f);
                if ((T21[1] >> kk) & 1u) wn += u;
            }
        }
    }

    // one float atomic per thread-slot; bins padded to 1 per 128B line (401 LTS slices)
    atomicAdd(&g_bins[d0 * 32], s0);
    if (has1) atomicAdd(&g_bins[d1 * 32], s1);

    // block-reduce scalars -> one float atomic each
    for (int o = 16; o; o >>= 1) {
        ct += __shfl_down_sync(0xffffffffu, ct, o);
        wn += __shfl_down_sync(0xffffffffu, wn, o);
    }
    __shared__ float red[2][8];
    int wid = tid >> 5, lane = tid & 31;
    if (lane == 0) { red[0][wid] = ct; red[1][wid] = wn; }
    __syncthreads();
    if (tid == 0) {
        float c = 0.f, ww = 0.f;
#pragma unroll
        for (int k = 0; k < 8; ++k) { c += red[0][k]; ww += red[1][k]; }
        atomicAdd(&g_scf[0],  c);
        atomicAdd(&g_scf[32], ww);
    }

    // ---------- last-block finalize ----------
    __threadfence();
    __shared__ unsigned int rank_sh;
    if (tid == 0) rank_sh = atomicAdd(&g_done, 1u);
    __syncthreads();
    if (rank_sh != NBLK - 1) return;
    __threadfence();

    const int t0 = tid, t1 = tid + 256;
    const bool hb1 = (t1 < L);

    float w0_ = 0.f, ld0 = 0.f, lp0 = 0.f;
    float w1_ = 0.f, ld1 = 0.f, lp1 = 0.f;
    float v4[4] = {0.f, 0.f, 0.f, 0.f};    // n, sum(w*ld), sum(w*lp), masked-sum
    {
        float binv = g_bins[t0 * 32];
        float cntp = (t0 == 0) ? (float)L : 2.0f * (float)(L - t0);
        float mc = binv / (cntp * (float)B);
        bool valid = (t0 >= 2) && isfinite(mc) && (mc > 0.0f);
        w0_ = valid ? 1.f : 0.f;
        ld0 = logf(fmaxf((float)t0, 1.0f));
        lp0 = logf((valid ? mc : 1.0f) + 1e-6f);
        v4[0] += w0_; v4[1] += w0_ * ld0; v4[2] += w0_ * lp0;
        if (t0 >= 2) v4[3] += binv;
    }
    if (hb1) {
        float binv = g_bins[t1 * 32];
        float cntp = 2.0f * (float)(L - t1);
        float mc = binv / (cntp * (float)B);
        bool valid = isfinite(mc) && (mc > 0.0f);   // t1 >= 256 >= 2 always
        w1_ = valid ? 1.f : 0.f;
        ld1 = logf((float)t1);
        lp1 = logf((valid ? mc : 1.0f) + 1e-6f);
        v4[0] += w1_; v4[1] += w1_ * ld1; v4[2] += w1_ * lp1;
        v4[3] += binv;
    }

    __shared__ float sc4[4][8];
    __shared__ float tot[4];
#pragma unroll
    for (int o = 16; o; o >>= 1)
#pragma unroll
        for (int q = 0; q < 4; ++q) v4[q] += __shfl_down_sync(0xffffffffu, v4[q], o);
    if (lane == 0) { sc4[0][wid] = v4[0]; sc4[1][wid] = v4[1]; sc4[2][wid] = v4[2]; sc4[3][wid] = v4[3]; }
    __syncthreads();
    if (tid < 4) {
        float sAcc = 0.f;
#pragma unroll
        for (int k = 0; k < 8; ++k) sAcc += sc4[tid][k];
        tot[tid] = sAcc;
    }
    __syncthreads();

    float n  = tot[0];
    float ns = fmaxf(n, 1.0f);
    float xm = tot[1] / ns, ym = tot[2] / ns;
    float msk = tot[3];

    float v2[2];
    v2[0] = w0_ * (ld0 - xm) * (lp0 - ym) + w1_ * (ld1 - xm) * (lp1 - ym);
    v2[1] = w0_ * (ld0 - xm) * (ld0 - xm) + w1_ * (ld1 - xm) * (ld1 - xm);
#pragma unroll
    for (int o = 16; o; o >>= 1)
#pragma unroll
        for (int q = 0; q < 2; ++q) v2[q] += __shfl_down_sync(0xffffffffu, v2[q], o);
    if (lane == 0) { sc4[0][wid] = v2[0]; sc4[1][wid] = v2[1]; }
    __syncthreads();
    if (tid == 0) {
        float num = 0.f, den = 0.f;
#pragma unroll
        for (int k = 0; k < 8; ++k) { num += sc4[0][k]; den += sc4[1][k]; }

        // distance decay
        double slope = (double)num / ((double)den + 1e-8);
        double dist  = (n >= 5.0f) ? (slope + 0.85) * (slope + 0.85) : 0.0;
        // ctcf
        double ncs   = (double)g_sci[0];
        double hinge = (double)g_scf[0] / (ncs + 1e-6);
        double ctcfl = (ncs < 1.0) ? 0.0 : hinge;
        // compartment
        double cw      = (double)g_sci[32];
        double cb      = 159600.0 * (double)B - cw;   // (L-1)(L-2) masked pairs per batch
        double within  = (double)g_scf[32] / fmax(cw, 1.0);
        double between = ((double)msk - (double)g_scf[32]) / fmax(cb, 1.0);
        double ratio   = within / (fabs(between) + 1e-6);
        double compl_  = fmax(1.5 - ratio, 0.0);

        out[0] = (float)dist;
        out[1] = (float)ctcfl;
        out[2] = (float)compl_;
        out[3] = (float)(dist + 0.5 * ctcfl + 0.5 * compl_);
    }

    // ---------- reset state for next replay ----------
    __syncthreads();
    g_bins[t0 * 32] = 0.f;
    if (hb1) g_bins[t1 * 32] = 0.f;
    if (tid < 2) { g_scf[tid * 32] = 0.f; g_sci[tid * 32] = 0; }
    if (tid == 0) g_done = 0u;
}

// ---------------- launch ----------------
extern "C" void kernel_launch(void* const* d_in, const int* in_sizes, int n_in,
                              void* d_out, int out_size) {
    const float* cm     = (const float*)d_in[0];   // (B, L, L) f32
    const float* logits = (const float*)d_in[1];   // (B, L, 2) f32
    const int*   ctcf   = (const int*)d_in[2];     // (B, L)    i32
    float*       out    = (float*)d_out;           // 4 f32

    prep_kernel<<<L + B, 512>>>(ctcf, logits);
    dim3 grid(NCHUNK, L);
    main_kernel<<<grid, 256>>>(cm, out);
}